// round 7
// baseline (speedup 1.0000x reference)
#include <cuda_runtime.h>
#include <cuda_bf16.h>
#include <math.h>

// Problem constants
#define BB 8
#define LL 4096
#define DD 512
#define HH 8
#define DH 64
#define DFF 2048
#define SK 128
#define UU 128
#define MROWS (BB*LL)   // 32768

// ---------------- scratch (device globals; no allocation allowed) -------------
__device__ __align__(16) float g_Q[MROWS*DD];
__device__ __align__(16) float g_K[MROWS*DD];
__device__ __align__(16) float g_V[MROWS*DD];
__device__ __align__(16) float g_ctx[MROWS*DD];
__device__ __align__(16) float g_attn[MROWS*DD];
__device__ __align__(16) float g_x1[MROWS*DD];
__device__ __align__(16) float g_ffh[MROWS*DFF];
__device__ __align__(16) float g_Mm[64*LL];
__device__              int   g_top[64*UU];
__device__ __align__(16) float g_mvpart[BB*32*DD];
__device__ __align__(16) float g_meanv[BB*DD];
__device__ __align__(16) float g_mzpart[64*4*UU*2];
__device__ __align__(16) float g_MZ[64*UU*2];
__device__ __align__(16) float g_cpart[64*UU*4*DH];
__device__ __align__(16) float g_ctxtop[64*UU*DH];

// ---------------- fp32 SGEMM: C[M,N] = A[M,K] @ B[K,N] + bias (+relu) --------
// BM=BN=128, BK=8, TM=TN=8, 256 threads. All dims divisible (M%128==0, N%128==0, K%8==0).
__global__ void __launch_bounds__(256) sgemm_bias(
    const float* __restrict__ A, const float* __restrict__ B,
    const float* __restrict__ bias, float* __restrict__ C,
    int M, int N, int K, int relu)
{
    __shared__ float As[8][128];
    __shared__ float Bs[8][128];
    const int brow = blockIdx.y, bcol = blockIdx.x;
    const int tid = threadIdx.x;
    const int tr = tid >> 4;        // 0..15
    const int tc = tid & 15;        // 0..15
    const int a_row  = tid >> 1;    // 0..127
    const int a_col4 = (tid & 1) * 4;
    const int b_row  = tid >> 5;    // 0..7
    const int b_col4 = (tid & 31) * 4;

    const float* Ab = A + (size_t)brow * 128 * K;
    const float* Bb = B + (size_t)bcol * 128;

    float acc[8][8];
    #pragma unroll
    for (int i = 0; i < 8; i++)
        #pragma unroll
        for (int j = 0; j < 8; j++) acc[i][j] = 0.f;

    for (int k0 = 0; k0 < K; k0 += 8) {
        float4 av = *(const float4*)(Ab + (size_t)a_row * K + k0 + a_col4);
        As[a_col4+0][a_row] = av.x; As[a_col4+1][a_row] = av.y;
        As[a_col4+2][a_row] = av.z; As[a_col4+3][a_row] = av.w;
        *(float4*)(&Bs[b_row][b_col4]) = *(const float4*)(Bb + (size_t)(k0 + b_row) * N + b_col4);
        __syncthreads();
        #pragma unroll
        for (int k = 0; k < 8; k++) {
            float ar[8], br[8];
            #pragma unroll
            for (int i = 0; i < 8; i++) ar[i] = As[k][tr*8 + i];
            #pragma unroll
            for (int j = 0; j < 8; j++) br[j] = Bs[k][tc*8 + j];
            #pragma unroll
            for (int i = 0; i < 8; i++)
                #pragma unroll
                for (int j = 0; j < 8; j++) acc[i][j] += ar[i] * br[j];
        }
        __syncthreads();
    }

    #pragma unroll
    for (int i = 0; i < 8; i++) {
        size_t row = (size_t)brow * 128 + tr*8 + i;
        #pragma unroll
        for (int j = 0; j < 8; j += 4) {
            int col = bcol * 128 + tc*8 + j;
            float4 v;
            v.x = acc[i][j+0] + bias[col+0];
            v.y = acc[i][j+1] + bias[col+1];
            v.z = acc[i][j+2] + bias[col+2];
            v.w = acc[i][j+3] + bias[col+3];
            if (relu) {
                v.x = fmaxf(v.x, 0.f); v.y = fmaxf(v.y, 0.f);
                v.z = fmaxf(v.z, 0.f); v.w = fmaxf(v.w, 0.f);
            }
            *(float4*)(C + row * N + col) = v;
        }
    }
}

// -------- sampled scores: M[b,h,l] = max_s(q.k_s) - mean_s(q.k_s) (no scale) --
// sample_idx dtype is ambiguous (int32 vs int64). Values are < 4096, so an
// int64 buffer viewed as int32 has ALL odd words zero; an int32 buffer has
// random samples at odd words (P(all zero) ~ 4096^-64 ~ 0). Detect per-block
// reading only the first 512 B (in-bounds for both dtypes); the int64 read
// path (up to 1024 B) is taken only after detection proves the buffer is int64.
__global__ void sampled_scores_kernel(const float* __restrict__ Q, const float* __restrict__ Km,
                                      const int* __restrict__ sidx, float* __restrict__ Mout)
{
    int l = blockIdx.x, bh = blockIdx.y;
    int b = bh >> 3, h = bh & 7, t = threadIdx.x;  // 128 threads
    __shared__ float qs[64];
    __shared__ float red[128];
    __shared__ int is64;
    const float* qrow = Q + ((size_t)(b*LL + l))*DD + h*DH;
    if (t < 64) qs[t] = qrow[t];
    if (t == 0) is64 = 1;
    __syncthreads();
    if ((t & 1) && sidx[t] != 0) is64 = 0;   // benign race: any writer writes 0
    __syncthreads();
    int li;
    if (is64) li = (int)(((const long long*)sidx)[t]) & (LL - 1);
    else      li = sidx[t] & (LL - 1);
    const float* krow = Km + ((size_t)(b*LL + li))*DD + h*DH;
    float dot = 0.f;
    #pragma unroll
    for (int d = 0; d < 64; d++) dot += qs[d]*krow[d];
    red[t] = dot; __syncthreads();
    for (int o = 64; o > 0; o >>= 1) { if (t < o) red[t] = fmaxf(red[t], red[t+o]); __syncthreads(); }
    float mx = red[0]; __syncthreads();
    red[t] = dot; __syncthreads();
    for (int o = 64; o > 0; o >>= 1) { if (t < o) red[t] += red[t+o]; __syncthreads(); }
    if (t == 0) Mout[(size_t)bh*LL + l] = mx - red[0]*(1.0f/128.0f);
}

// -------- exact top-128 per (b,h) via bitonic sort of 4096 pairs --------------
__global__ void __launch_bounds__(512) topk_kernel(const float* __restrict__ Mv, int* __restrict__ top)
{
    __shared__ float val[4096];
    __shared__ int   idx[4096];
    int bh = blockIdx.x, t = threadIdx.x;  // 512 threads
    for (int i = t; i < 4096; i += 512) { val[i] = Mv[(size_t)bh*LL + i]; idx[i] = i; }
    __syncthreads();
    for (int k = 2; k <= 4096; k <<= 1) {
        for (int j = k >> 1; j > 0; j >>= 1) {
            for (int i = t; i < 4096; i += 512) {
                int ixj = i ^ j;
                if (ixj > i) {
                    bool desc = ((i & k) == 0);
                    float vi = val[i], vj = val[ixj];
                    if ((vi < vj) == desc) {
                        val[i] = vj; val[ixj] = vi;
                        int tmp = idx[i]; idx[i] = idx[ixj]; idx[ixj] = tmp;
                    }
                }
            }
            __syncthreads();
        }
    }
    if (t < 128) top[bh*UU + t] = idx[t];
}

// -------- meanV over L (two-stage, deterministic) -----------------------------
__global__ void meanv_part_kernel(const float* __restrict__ V, float* __restrict__ part)
{
    int chunk = blockIdx.x, b = blockIdx.y, t = threadIdx.x;  // 512 threads
    float s = 0.f;
    int l0 = chunk * 128;
    for (int l = l0; l < l0 + 128; l++) s += V[((size_t)(b*LL + l))*DD + t];
    part[((size_t)b*32 + chunk)*DD + t] = s;
}
__global__ void meanv_reduce_kernel(const float* __restrict__ part, float* __restrict__ meanv)
{
    int b = blockIdx.x, t = threadIdx.x;  // 512 threads
    float s = 0.f;
    for (int c = 0; c < 32; c++) s += part[((size_t)b*32 + c)*DD + t];
    meanv[b*DD + t] = s * (1.f/4096.f);
}

// -------- softmax pass 1: chunked online (m,z) per top query ------------------
__global__ void __launch_bounds__(128) attn_mz_kernel(
    const float* __restrict__ Q, const float* __restrict__ Km,
    const int* __restrict__ top, float* __restrict__ mz)
{
    __shared__ float qs[128][65];
    __shared__ float kt[32][65];
    int chunk = blockIdx.x, bh = blockIdx.y;
    int b = bh >> 3, h = bh & 7, t = threadIdx.x;
    const float scale = 0.125f;
    for (int i = t; i < 128*64; i += 128) {
        int u = i >> 6, d = i & 63;
        int lq = top[bh*UU + u] & (LL - 1);
        qs[u][d] = Q[((size_t)(b*LL + lq))*DD + h*DH + d] * scale;
    }
    __syncthreads();
    float m = -1e30f, z = 0.f;
    int l0 = chunk * 1024;
    for (int lt = 0; lt < 1024; lt += 32) {
        for (int i = t; i < 32*64; i += 128) {
            int r = i >> 6, d = i & 63;
            kt[r][d] = Km[((size_t)(b*LL + l0 + lt + r))*DD + h*DH + d];
        }
        __syncthreads();
        for (int r = 0; r < 32; r++) {
            float s = 0.f;
            #pragma unroll
            for (int d = 0; d < 64; d++) s += qs[t][d]*kt[r][d];
            if (s > m) { z = z*__expf(m - s) + 1.f; m = s; }
            else       { z += __expf(s - m); }
        }
        __syncthreads();
    }
    mz[(((size_t)bh*4 + chunk)*UU + t)*2 + 0] = m;
    mz[(((size_t)bh*4 + chunk)*UU + t)*2 + 1] = z;
}

__global__ void attn_mz_combine(const float* __restrict__ mz, float* __restrict__ MZ)
{
    int bh = blockIdx.x, t = threadIdx.x;  // 128
    float m = -1e30f, z = 0.f;
    for (int c = 0; c < 4; c++) {
        float mc = mz[(((size_t)bh*4 + c)*UU + t)*2 + 0];
        float zc = mz[(((size_t)bh*4 + c)*UU + t)*2 + 1];
        float mm = fmaxf(m, mc);
        z = z*__expf(m - mm) + zc*__expf(mc - mm);
        m = mm;
    }
    MZ[((size_t)bh*UU + t)*2 + 0] = m;
    MZ[((size_t)bh*UU + t)*2 + 1] = z;
}

// -------- softmax pass 2: weighted V sum, 16 queries per block, L chunked -----
__global__ void __launch_bounds__(128) attn_ctx_kernel(
    const float* __restrict__ Q, const float* __restrict__ Km, const float* __restrict__ V,
    const int* __restrict__ top, const float* __restrict__ MZ, float* __restrict__ cpart)
{
    __shared__ float qs[16][65];
    __shared__ float kt[64][65];
    __shared__ float vt[64][66];
    __shared__ float ps[16][64];
    __shared__ float Ms[16];
    int ut = blockIdx.x, bh = blockIdx.y, chunk = blockIdx.z;
    int b = bh >> 3, h = bh & 7, t = threadIdx.x;
    const float scale = 0.125f;
    for (int i = t; i < 16*64; i += 128) {
        int u = i >> 6, d = i & 63;
        int lq = top[bh*UU + ut*16 + u] & (LL - 1);
        qs[u][d] = Q[((size_t)(b*LL + lq))*DD + h*DH + d] * scale;
    }
    if (t < 16) Ms[t] = MZ[((size_t)bh*UU + ut*16 + t)*2 + 0];
    __syncthreads();
    int qi = t >> 3, d0 = (t & 7) * 8;
    float acc[8] = {0,0,0,0,0,0,0,0};
    int l0 = chunk * 1024;
    for (int lt = 0; lt < 1024; lt += 64) {
        for (int i = t; i < 64*64; i += 128) {
            int r = i >> 6, d = i & 63;
            size_t base = ((size_t)(b*LL + l0 + lt + r))*DD + h*DH + d;
            kt[r][d] = Km[base];
            vt[r][d] = V[base];
        }
        __syncthreads();
        {
            int lbase = t & 7;
            #pragma unroll
            for (int i = 0; i < 8; i++) {
                int r = lbase*8 + i;
                float s = 0.f;
                #pragma unroll
                for (int d = 0; d < 64; d++) s += qs[qi][d]*kt[r][d];
                ps[qi][r] = __expf(s - Ms[qi]);
            }
        }
        __syncthreads();
        for (int r = 0; r < 64; r++) {
            float p = ps[qi][r];
            #pragma unroll
            for (int j = 0; j < 8; j++) acc[j] += p * vt[r][d0+j];
        }
        __syncthreads();
    }
    float* o = cpart + ((((size_t)bh*UU + ut*16 + qi)*4 + chunk)*DH) + d0;
    #pragma unroll
    for (int j = 0; j < 8; j++) o[j] = acc[j];
}

__global__ void attn_ctx_combine(const float* __restrict__ cpart, const float* __restrict__ MZ,
                                 float* __restrict__ ctxtop)
{
    int i = blockIdx.x*256 + threadIdx.x;  // over 64*128*64
    if (i >= 64*UU*DH) return;
    int d = i & 63, u = (i >> 6) & 127, bh = i >> 13;
    float s = 0.f;
    for (int c = 0; c < 4; c++) s += cpart[(((size_t)bh*UU + u)*4 + c)*DH + d];
    float Z = MZ[((size_t)bh*UU + u)*2 + 1];
    ctxtop[i] = s / Z;
}

// -------- ctx assembly: broadcast meanV then scatter top contexts -------------
__global__ void broadcast_meanv(const float* __restrict__ meanv, float* __restrict__ ctx)
{
    size_t i = (size_t)blockIdx.x*256 + threadIdx.x;
    if (i >= (size_t)MROWS*DD) return;
    int col = (int)(i & 511);
    int row = (int)(i >> 9);
    int b = row >> 12;
    ctx[i] = meanv[b*DD + col];
}
__global__ void scatter_ctxtop(const float* __restrict__ ctxtop, const int* __restrict__ top,
                               float* __restrict__ ctx)
{
    int u = blockIdx.x, bh = blockIdx.y, t = threadIdx.x;  // 64 threads
    int b = bh >> 3, h = bh & 7;
    int l = top[bh*UU + u] & (LL - 1);
    ctx[((size_t)(b*LL + l))*DD + h*DH + t] = ctxtop[((size_t)bh*UU + u)*DH + t];
}

// -------- fused residual-add + LayerNorm --------------------------------------
__global__ void __launch_bounds__(128) add_ln_kernel(
    const float* __restrict__ a, const float* __restrict__ r,
    const float* __restrict__ g, const float* __restrict__ be,
    float* __restrict__ out)
{
    int row = blockIdx.x, t = threadIdx.x;  // 128 threads, D=512
    __shared__ float red[128];
    size_t base = (size_t)row * DD;
    float4 av = *(const float4*)(a + base + t*4);
    float4 rv = *(const float4*)(r + base + t*4);
    float x0 = av.x + rv.x, x1 = av.y + rv.y, x2 = av.z + rv.z, x3 = av.w + rv.w;
    red[t] = x0 + x1 + x2 + x3; __syncthreads();
    for (int o = 64; o > 0; o >>= 1) { if (t < o) red[t] += red[t+o]; __syncthreads(); }
    float mean = red[0] * (1.f/512.f); __syncthreads();
    float d0 = x0 - mean, d1 = x1 - mean, d2 = x2 - mean, d3 = x3 - mean;
    red[t] = d0*d0 + d1*d1 + d2*d2 + d3*d3; __syncthreads();
    for (int o = 64; o > 0; o >>= 1) { if (t < o) red[t] += red[t+o]; __syncthreads(); }
    float inv = rsqrtf(red[0]*(1.f/512.f) + 1e-6f);
    float4 gv = *(const float4*)(g + t*4);
    float4 bv = *(const float4*)(be + t*4);
    float4 y;
    y.x = d0*inv*gv.x + bv.x;
    y.y = d1*inv*gv.y + bv.y;
    y.z = d2*inv*gv.z + bv.z;
    y.w = d3*inv*gv.w + bv.w;
    *(float4*)(out + base + t*4) = y;
}

// ------------------------------- launch ---------------------------------------
extern "C" void kernel_launch(void* const* d_in, const int* in_sizes, int n_in,
                              void* d_out, int out_size)
{
    const float* x   = (const float*)d_in[0];
    const float* Wq  = (const float*)d_in[1];  const float* bq  = (const float*)d_in[2];
    const float* Wk  = (const float*)d_in[3];  const float* bk  = (const float*)d_in[4];
    const float* Wv  = (const float*)d_in[5];  const float* bv  = (const float*)d_in[6];
    const float* Wo  = (const float*)d_in[7];  const float* bo  = (const float*)d_in[8];
    const float* g1  = (const float*)d_in[9];  const float* b1  = (const float*)d_in[10];
    const float* W1f = (const float*)d_in[11]; const float* b1f = (const float*)d_in[12];
    const float* W2f = (const float*)d_in[13]; const float* b2f = (const float*)d_in[14];
    const float* g2  = (const float*)d_in[15]; const float* b2  = (const float*)d_in[16];
    const int*   sidx = (const int*)d_in[17];   // dtype-adaptive read in kernel
    float* out = (float*)d_out;

    float *Qp, *Kp, *Vp, *ctxp, *attnp, *x1p, *ffhp, *Mp, *mvpp, *mvp, *mzp, *MZp, *cpp, *ctp;
    int* topp;
    cudaGetSymbolAddress((void**)&Qp,    g_Q);
    cudaGetSymbolAddress((void**)&Kp,    g_K);
    cudaGetSymbolAddress((void**)&Vp,    g_V);
    cudaGetSymbolAddress((void**)&ctxp,  g_ctx);
    cudaGetSymbolAddress((void**)&attnp, g_attn);
    cudaGetSymbolAddress((void**)&x1p,   g_x1);
    cudaGetSymbolAddress((void**)&ffhp,  g_ffh);
    cudaGetSymbolAddress((void**)&Mp,    g_Mm);
    cudaGetSymbolAddress((void**)&topp,  g_top);
    cudaGetSymbolAddress((void**)&mvpp,  g_mvpart);
    cudaGetSymbolAddress((void**)&mvp,   g_meanv);
    cudaGetSymbolAddress((void**)&mzp,   g_mzpart);
    cudaGetSymbolAddress((void**)&MZp,   g_MZ);
    cudaGetSymbolAddress((void**)&cpp,   g_cpart);
    cudaGetSymbolAddress((void**)&ctp,   g_ctxtop);

    // Q, K, V projections
    sgemm_bias<<<dim3(DD/128, MROWS/128), 256>>>(x, Wq, bq, Qp, MROWS, DD, DD, 0);
    sgemm_bias<<<dim3(DD/128, MROWS/128), 256>>>(x, Wk, bk, Kp, MROWS, DD, DD, 0);
    sgemm_bias<<<dim3(DD/128, MROWS/128), 256>>>(x, Wv, bv, Vp, MROWS, DD, DD, 0);

    // sparsity metric + top-k
    sampled_scores_kernel<<<dim3(LL, 64), 128>>>(Qp, Kp, sidx, Mp);
    topk_kernel<<<64, 512>>>(Mp, topp);

    // meanV
    meanv_part_kernel<<<dim3(32, BB), 512>>>(Vp, mvpp);
    meanv_reduce_kernel<<<BB, 512>>>(mvpp, mvp);

    // top-query attention (two-pass softmax, chunked)
    attn_mz_kernel<<<dim3(4, 64), 128>>>(Qp, Kp, topp, mzp);
    attn_mz_combine<<<64, 128>>>(mzp, MZp);
    attn_ctx_kernel<<<dim3(8, 64, 4), 128>>>(Qp, Kp, Vp, topp, MZp, cpp);
    attn_ctx_combine<<<(64*UU*DH + 255)/256, 256>>>(cpp, MZp, ctp);

    // assemble ctx and output projection
    broadcast_meanv<<<(int)(((size_t)MROWS*DD + 255)/256), 256>>>(mvp, ctxp);
    scatter_ctxtop<<<dim3(UU, 64), 64>>>(ctp, topp, ctxp);
    sgemm_bias<<<dim3(DD/128, MROWS/128), 256>>>(ctxp, Wo, bo, attnp, MROWS, DD, DD, 0);

    // LN1
    add_ln_kernel<<<MROWS, 128>>>(x, attnp, g1, b1, x1p);

    // FFN
    sgemm_bias<<<dim3(DFF/128, MROWS/128), 256>>>(x1p, W1f, b1f, ffhp, MROWS, DFF, DD, 1);
    sgemm_bias<<<dim3(DD/128, MROWS/128), 256>>>(ffhp, W2f, b2f, attnp, MROWS, DD, DFF, 0);

    // LN2 -> output
    add_ln_kernel<<<MROWS, 128>>>(x1p, attnp, g2, b2, out);
}

// round 10
// speedup vs baseline: 1.1959x; 1.1959x over previous
#include <cuda_runtime.h>
#include <cuda_bf16.h>
#include <math.h>
#include <stdint.h>

// Problem constants
#define BB 8
#define LL 4096
#define DD 512
#define HH 8
#define DH 64
#define DFF 2048
#define SK 128
#define UU 128
#define MROWS (BB*LL)   // 32768

// ---------------- scratch (device globals; no allocation allowed) -------------
__device__ __align__(16) float g_Q[MROWS*DD];
__device__ __align__(16) float g_K[MROWS*DD];
__device__ __align__(16) float g_V[MROWS*DD];
__device__ __align__(16) float g_ctx[MROWS*DD];
__device__ __align__(16) float g_attn[MROWS*DD];
__device__ __align__(16) float g_x1[MROWS*DD];
__device__ __align__(16) float g_ffh[MROWS*DFF];
__device__ __align__(16) float g_Mm[64*LL];
__device__              int   g_top[64*UU];
__device__ __align__(16) float g_mvpart[BB*32*DD];
__device__ __align__(16) float g_meanv[BB*DD];
__device__ __align__(16) float g_mzpart[64*4*UU*2];
__device__ __align__(16) float g_MZ[64*UU*2];
__device__ __align__(16) float g_cpart[64*UU*4*DH];
__device__ __align__(16) float g_ctxtop[64*UU*DH];

// bf16 split scratch
__device__ __align__(16) __nv_bfloat16 g_act_h[MROWS*DFF];
__device__ __align__(16) __nv_bfloat16 g_act_l[MROWS*DFF];
__device__ __align__(16) __nv_bfloat16 g_wq_h[DD*DD],  g_wq_l[DD*DD];
__device__ __align__(16) __nv_bfloat16 g_wk_h[DD*DD],  g_wk_l[DD*DD];
__device__ __align__(16) __nv_bfloat16 g_wv_h[DD*DD],  g_wv_l[DD*DD];
__device__ __align__(16) __nv_bfloat16 g_wo_h[DD*DD],  g_wo_l[DD*DD];
__device__ __align__(16) __nv_bfloat16 g_w1_h[DFF*DD], g_w1_l[DFF*DD];
__device__ __align__(16) __nv_bfloat16 g_w2_h[DD*DFF], g_w2_l[DD*DFF];

// ===================== sm_80-baseline tensor helpers ==========================
__device__ __forceinline__ uint32_t smem_u32(const void* p) {
    uint32_t a;
    asm("{ .reg .u64 t; cvta.to.shared.u64 t, %1; cvt.u32.u64 %0, t; }" : "=r"(a) : "l"(p));
    return a;
}
__device__ __forceinline__ void cpa16(uint32_t s, const void* g) {
    asm volatile("cp.async.cg.shared.global [%0], [%1], 16;" :: "r"(s), "l"(g) : "memory");
}
__device__ __forceinline__ void ldm_x4(uint32_t* r, uint32_t a) {
    asm volatile("ldmatrix.sync.aligned.m8n8.x4.shared.b16 {%0,%1,%2,%3}, [%4];"
                 : "=r"(r[0]), "=r"(r[1]), "=r"(r[2]), "=r"(r[3]) : "r"(a));
}
__device__ __forceinline__ void ldm_x2(uint32_t* r, uint32_t a) {
    asm volatile("ldmatrix.sync.aligned.m8n8.x2.shared.b16 {%0,%1}, [%2];"
                 : "=r"(r[0]), "=r"(r[1]) : "r"(a));
}
__device__ __forceinline__ void mma_bf16(float* c, const uint32_t* a, const uint32_t* b) {
    asm volatile("mma.sync.aligned.m16n8k16.row.col.f32.bf16.bf16.f32 "
                 "{%0,%1,%2,%3}, {%4,%5,%6,%7}, {%8,%9}, {%0,%1,%2,%3};"
                 : "+f"(c[0]), "+f"(c[1]), "+f"(c[2]), "+f"(c[3])
                 : "r"(a[0]), "r"(a[1]), "r"(a[2]), "r"(a[3]), "r"(b[0]), "r"(b[1]));
}

// ============ split-bf16 tensor-core GEMM: C = A @ W + bias (+relu) ==========
// A hi/lo [M][K] bf16; W hi/lo TRANSPOSED [N][K] bf16.
// 128x128 block, 8 warps (2x4), warp tile 64x32, BK=64, double-buffered cp.async.
// Dynamic smem: 2 stages * 4 tiles * 16KB = 131072 B. SW128 swizzle on 128B rows.
__global__ void __launch_bounds__(256) gemm_tc(
    const __nv_bfloat16* __restrict__ Ah, const __nv_bfloat16* __restrict__ Al,
    const __nv_bfloat16* __restrict__ Bh, const __nv_bfloat16* __restrict__ Bl,
    const float* __restrict__ bias, float* __restrict__ C,
    int M, int N, int K, int relu)
{
    extern __shared__ char smem[];
    const int tid = threadIdx.x, lid = tid & 31, wid = tid >> 5;
    const int warp_m = wid & 1, warp_n = wid >> 1;   // 2 x 4 warps
    const int m0 = blockIdx.y * 128, n0 = blockIdx.x * 128;
    const uint32_t sb = smem_u32(smem);
    const int nch = K >> 6;

    auto issue = [&](int c, int s) {
        const int k0 = c << 6;
        const uint32_t base = sb + s * 65536;
        for (int i = tid; i < 1024; i += 256) {
            int row = i >> 3, seg = i & 7;
            uint32_t off = row * 128 + seg * 16;
            uint32_t sw = off ^ ((off >> 3) & 0x70);
            size_t ga = (size_t)(m0 + row) * K + k0 + seg * 8;
            size_t gb = (size_t)(n0 + row) * K + k0 + seg * 8;
            cpa16(base + sw,         Ah + ga);
            cpa16(base + 16384 + sw, Al + ga);
            cpa16(base + 32768 + sw, Bh + gb);
            cpa16(base + 49152 + sw, Bl + gb);
        }
        asm volatile("cp.async.commit_group;" ::: "memory");
    };

    float acc[4][4][4];
    #pragma unroll
    for (int mi = 0; mi < 4; mi++)
        #pragma unroll
        for (int ni = 0; ni < 4; ni++)
            #pragma unroll
            for (int f = 0; f < 4; f++) acc[mi][ni][f] = 0.f;

    issue(0, 0);
    for (int c = 0; c < nch; c++) {
        if (c + 1 < nch) {
            issue(c + 1, (c + 1) & 1);
            asm volatile("cp.async.wait_group 1;" ::: "memory");
        } else {
            asm volatile("cp.async.wait_group 0;" ::: "memory");
        }
        __syncthreads();
        const uint32_t base = sb + (c & 1) * 65536;
        #pragma unroll
        for (int ks = 0; ks < 4; ks++) {
            uint32_t ah[4][4], alo[4][4], bh[4][2], blo[4][2];
            #pragma unroll
            for (int mi = 0; mi < 4; mi++) {
                int row = warp_m * 64 + mi * 16 + (lid & 15);
                uint32_t off = row * 128 + ks * 32 + (lid >> 4) * 16;
                uint32_t sw = off ^ ((off >> 3) & 0x70);
                ldm_x4(ah[mi],  base + sw);
                ldm_x4(alo[mi], base + 16384 + sw);
            }
            #pragma unroll
            for (int ni = 0; ni < 4; ni++) {
                int row = warp_n * 32 + ni * 8 + (lid & 7);
                uint32_t off = row * 128 + ks * 32 + ((lid >> 3) & 1) * 16;
                uint32_t sw = off ^ ((off >> 3) & 0x70);
                ldm_x2(bh[ni],  base + 32768 + sw);
                ldm_x2(blo[ni], base + 49152 + sw);
            }
            #pragma unroll
            for (int mi = 0; mi < 4; mi++)
                #pragma unroll
                for (int ni = 0; ni < 4; ni++) {
                    mma_bf16(acc[mi][ni], ah[mi],  bh[ni]);
                    mma_bf16(acc[mi][ni], ah[mi],  blo[ni]);
                    mma_bf16(acc[mi][ni], alo[mi], bh[ni]);
                }
        }
        __syncthreads();
    }

    // epilogue: C frag mapping c0:(l/4, 2*(l%4)) c1:+1col c2:+8row c3:+8row+1col
    const int grow = m0 + warp_m * 64;
    const int gcol = n0 + warp_n * 32;
    #pragma unroll
    for (int mi = 0; mi < 4; mi++)
        #pragma unroll
        for (int ni = 0; ni < 4; ni++) {
            int r = grow + mi * 16 + (lid >> 2);
            int cc = gcol + ni * 8 + (lid & 3) * 2;
            float b0 = bias[cc], b1 = bias[cc + 1];
            float v0 = acc[mi][ni][0] + b0;
            float v1 = acc[mi][ni][1] + b1;
            float v2 = acc[mi][ni][2] + b0;
            float v3 = acc[mi][ni][3] + b1;
            if (relu) {
                v0 = fmaxf(v0, 0.f); v1 = fmaxf(v1, 0.f);
                v2 = fmaxf(v2, 0.f); v3 = fmaxf(v3, 0.f);
            }
            C[(size_t)r * N + cc]           = v0;
            C[(size_t)r * N + cc + 1]       = v1;
            C[(size_t)(r + 8) * N + cc]     = v2;
            C[(size_t)(r + 8) * N + cc + 1] = v3;
        }
}

// ---------------- conversion kernels -----------------------------------------
__global__ void split_convert(const float* __restrict__ in,
                              __nv_bfloat16* __restrict__ hi, __nv_bfloat16* __restrict__ lo,
                              int n)
{
    int i = blockIdx.x * 256 + threadIdx.x;
    if (i >= n) return;
    float v = in[i];
    __nv_bfloat16 h = __float2bfloat16(v);
    hi[i] = h;
    lo[i] = __float2bfloat16(v - __bfloat162float(h));
}
// W [K,N] row-major -> out [N,K] split
__global__ void wsplit_t(const float* __restrict__ W,
                         __nv_bfloat16* __restrict__ hi, __nv_bfloat16* __restrict__ lo,
                         int K, int N)
{
    int i = blockIdx.x * 256 + threadIdx.x;
    if (i >= K * N) return;
    int nn = i / K, kk = i - nn * K;
    float v = W[(size_t)kk * N + nn];
    __nv_bfloat16 h = __float2bfloat16(v);
    hi[i] = h;
    lo[i] = __float2bfloat16(v - __bfloat162float(h));
}

// ======================= attention-side kernels (unchanged) ===================
__global__ void sampled_scores_kernel(const float* __restrict__ Q, const float* __restrict__ Km,
                                      const int* __restrict__ sidx, float* __restrict__ Mout)
{
    int l = blockIdx.x, bh = blockIdx.y;
    int b = bh >> 3, h = bh & 7, t = threadIdx.x;  // 128 threads
    __shared__ float qs[64];
    __shared__ float red[128];
    __shared__ int is64;
    const float* qrow = Q + ((size_t)(b*LL + l))*DD + h*DH;
    if (t < 64) qs[t] = qrow[t];
    if (t == 0) is64 = 1;
    __syncthreads();
    if ((t & 1) && sidx[t] != 0) is64 = 0;
    __syncthreads();
    int li;
    if (is64) li = (int)(((const long long*)sidx)[t]) & (LL - 1);
    else      li = sidx[t] & (LL - 1);
    const float* krow = Km + ((size_t)(b*LL + li))*DD + h*DH;
    float dot = 0.f;
    #pragma unroll
    for (int d = 0; d < 64; d++) dot += qs[d]*krow[d];
    red[t] = dot; __syncthreads();
    for (int o = 64; o > 0; o >>= 1) { if (t < o) red[t] = fmaxf(red[t], red[t+o]); __syncthreads(); }
    float mx = red[0]; __syncthreads();
    red[t] = dot; __syncthreads();
    for (int o = 64; o > 0; o >>= 1) { if (t < o) red[t] += red[t+o]; __syncthreads(); }
    if (t == 0) Mout[(size_t)bh*LL + l] = mx - red[0]*(1.0f/128.0f);
}

__global__ void __launch_bounds__(512) topk_kernel(const float* __restrict__ Mv, int* __restrict__ top)
{
    __shared__ float val[4096];
    __shared__ int   idx[4096];
    int bh = blockIdx.x, t = threadIdx.x;
    for (int i = t; i < 4096; i += 512) { val[i] = Mv[(size_t)bh*LL + i]; idx[i] = i; }
    __syncthreads();
    for (int k = 2; k <= 4096; k <<= 1) {
        for (int j = k >> 1; j > 0; j >>= 1) {
            for (int i = t; i < 4096; i += 512) {
                int ixj = i ^ j;
                if (ixj > i) {
                    bool desc = ((i & k) == 0);
                    float vi = val[i], vj = val[ixj];
                    if ((vi < vj) == desc) {
                        val[i] = vj; val[ixj] = vi;
                        int tmp = idx[i]; idx[i] = idx[ixj]; idx[ixj] = tmp;
                    }
                }
            }
            __syncthreads();
        }
    }
    if (t < 128) top[bh*UU + t] = idx[t];
}

__global__ void meanv_part_kernel(const float* __restrict__ V, float* __restrict__ part)
{
    int chunk = blockIdx.x, b = blockIdx.y, t = threadIdx.x;
    float s = 0.f;
    int l0 = chunk * 128;
    for (int l = l0; l < l0 + 128; l++) s += V[((size_t)(b*LL + l))*DD + t];
    part[((size_t)b*32 + chunk)*DD + t] = s;
}
__global__ void meanv_reduce_kernel(const float* __restrict__ part, float* __restrict__ meanv)
{
    int b = blockIdx.x, t = threadIdx.x;
    float s = 0.f;
    for (int c = 0; c < 32; c++) s += part[((size_t)b*32 + c)*DD + t];
    meanv[b*DD + t] = s * (1.f/4096.f);
}

__global__ void __launch_bounds__(128) attn_mz_kernel(
    const float* __restrict__ Q, const float* __restrict__ Km,
    const int* __restrict__ top, float* __restrict__ mz)
{
    __shared__ float qs[128][65];
    __shared__ float kt[32][65];
    int chunk = blockIdx.x, bh = blockIdx.y;
    int b = bh >> 3, h = bh & 7, t = threadIdx.x;
    const float scale = 0.125f;
    for (int i = t; i < 128*64; i += 128) {
        int u = i >> 6, d = i & 63;
        int lq = top[bh*UU + u] & (LL - 1);
        qs[u][d] = Q[((size_t)(b*LL + lq))*DD + h*DH + d] * scale;
    }
    __syncthreads();
    float m = -1e30f, z = 0.f;
    int l0 = chunk * 1024;
    for (int lt = 0; lt < 1024; lt += 32) {
        for (int i = t; i < 32*64; i += 128) {
            int r = i >> 6, d = i & 63;
            kt[r][d] = Km[((size_t)(b*LL + l0 + lt + r))*DD + h*DH + d];
        }
        __syncthreads();
        for (int r = 0; r < 32; r++) {
            float s = 0.f;
            #pragma unroll
            for (int d = 0; d < 64; d++) s += qs[t][d]*kt[r][d];
            if (s > m) { z = z*__expf(m - s) + 1.f; m = s; }
            else       { z += __expf(s - m); }
        }
        __syncthreads();
    }
    mz[(((size_t)bh*4 + chunk)*UU + t)*2 + 0] = m;
    mz[(((size_t)bh*4 + chunk)*UU + t)*2 + 1] = z;
}

__global__ void attn_mz_combine(const float* __restrict__ mz, float* __restrict__ MZ)
{
    int bh = blockIdx.x, t = threadIdx.x;
    float m = -1e30f, z = 0.f;
    for (int c = 0; c < 4; c++) {
        float mc = mz[(((size_t)bh*4 + c)*UU + t)*2 + 0];
        float zc = mz[(((size_t)bh*4 + c)*UU + t)*2 + 1];
        float mm = fmaxf(m, mc);
        z = z*__expf(m - mm) + zc*__expf(mc - mm);
        m = mm;
    }
    MZ[((size_t)bh*UU + t)*2 + 0] = m;
    MZ[((size_t)bh*UU + t)*2 + 1] = z;
}

__global__ void __launch_bounds__(128) attn_ctx_kernel(
    const float* __restrict__ Q, const float* __restrict__ Km, const float* __restrict__ V,
    const int* __restrict__ top, const float* __restrict__ MZ, float* __restrict__ cpart)
{
    __shared__ float qs[16][65];
    __shared__ float kt[64][65];
    __shared__ float vt[64][66];
    __shared__ float ps[16][64];
    __shared__ float Ms[16];
    int ut = blockIdx.x, bh = blockIdx.y, chunk = blockIdx.z;
    int b = bh >> 3, h = bh & 7, t = threadIdx.x;
    const float scale = 0.125f;
    for (int i = t; i < 16*64; i += 128) {
        int u = i >> 6, d = i & 63;
        int lq = top[bh*UU + ut*16 + u] & (LL - 1);
        qs[u][d] = Q[((size_t)(b*LL + lq))*DD + h*DH + d] * scale;
    }
    if (t < 16) Ms[t] = MZ[((size_t)bh*UU + ut*16 + t)*2 + 0];
    __syncthreads();
    int qi = t >> 3, d0 = (t & 7) * 8;
    float acc[8] = {0,0,0,0,0,0,0,0};
    int l0 = chunk * 1024;
    for (int lt = 0; lt < 1024; lt += 64) {
        for (int i = t; i < 64*64; i += 128) {
            int r = i >> 6, d = i & 63;
            size_t base = ((size_t)(b*LL + l0 + lt + r))*DD + h*DH + d;
            kt[r][d] = Km[base];
            vt[r][d] = V[base];
        }
        __syncthreads();
        {
            int lbase = t & 7;
            #pragma unroll
            for (int i = 0; i < 8; i++) {
                int r = lbase*8 + i;
                float s = 0.f;
                #pragma unroll
                for (int d = 0; d < 64; d++) s += qs[qi][d]*kt[r][d];
                ps[qi][r] = __expf(s - Ms[qi]);
            }
        }
        __syncthreads();
        for (int r = 0; r < 64; r++) {
            float p = ps[qi][r];
            #pragma unroll
            for (int j = 0; j < 8; j++) acc[j] += p * vt[r][d0+j];
        }
        __syncthreads();
    }
    float* o = cpart + ((((size_t)bh*UU + ut*16 + qi)*4 + chunk)*DH) + d0;
    #pragma unroll
    for (int j = 0; j < 8; j++) o[j] = acc[j];
}

__global__ void attn_ctx_combine(const float* __restrict__ cpart, const float* __restrict__ MZ,
                                 float* __restrict__ ctxtop)
{
    int i = blockIdx.x*256 + threadIdx.x;
    if (i >= 64*UU*DH) return;
    int d = i & 63, u = (i >> 6) & 127, bh = i >> 13;
    float s = 0.f;
    for (int c = 0; c < 4; c++) s += cpart[(((size_t)bh*UU + u)*4 + c)*DH + d];
    float Z = MZ[((size_t)bh*UU + u)*2 + 1];
    ctxtop[i] = s / Z;
}

__global__ void broadcast_meanv(const float* __restrict__ meanv, float* __restrict__ ctx)
{
    size_t i = (size_t)blockIdx.x*256 + threadIdx.x;
    if (i >= (size_t)MROWS*DD) return;
    int col = (int)(i & 511);
    int row = (int)(i >> 9);
    int b = row >> 12;
    ctx[i] = meanv[b*DD + col];
}
__global__ void scatter_ctxtop(const float* __restrict__ ctxtop, const int* __restrict__ top,
                               float* __restrict__ ctx)
{
    int u = blockIdx.x, bh = blockIdx.y, t = threadIdx.x;
    int b = bh >> 3, h = bh & 7;
    int l = top[bh*UU + u] & (LL - 1);
    ctx[((size_t)(b*LL + l))*DD + h*DH + t] = ctxtop[((size_t)bh*UU + u)*DH + t];
}

__global__ void __launch_bounds__(128) add_ln_kernel(
    const float* __restrict__ a, const float* __restrict__ r,
    const float* __restrict__ g, const float* __restrict__ be,
    float* __restrict__ out)
{
    int row = blockIdx.x, t = threadIdx.x;
    __shared__ float red[128];
    size_t base = (size_t)row * DD;
    float4 av = *(const float4*)(a + base + t*4);
    float4 rv = *(const float4*)(r + base + t*4);
    float x0 = av.x + rv.x, x1 = av.y + rv.y, x2 = av.z + rv.z, x3 = av.w + rv.w;
    red[t] = x0 + x1 + x2 + x3; __syncthreads();
    for (int o = 64; o > 0; o >>= 1) { if (t < o) red[t] += red[t+o]; __syncthreads(); }
    float mean = red[0] * (1.f/512.f); __syncthreads();
    float d0 = x0 - mean, d1 = x1 - mean, d2 = x2 - mean, d3 = x3 - mean;
    red[t] = d0*d0 + d1*d1 + d2*d2 + d3*d3; __syncthreads();
    for (int o = 64; o > 0; o >>= 1) { if (t < o) red[t] += red[t+o]; __syncthreads(); }
    float inv = rsqrtf(red[0]*(1.f/512.f) + 1e-6f);
    float4 gv = *(const float4*)(g + t*4);
    float4 bv = *(const float4*)(be + t*4);
    float4 y;
    y.x = d0*inv*gv.x + bv.x;
    y.y = d1*inv*gv.y + bv.y;
    y.z = d2*inv*gv.z + bv.z;
    y.w = d3*inv*gv.w + bv.w;
    *(float4*)(out + base + t*4) = y;
}

// ------------------------------- launch ---------------------------------------
extern "C" void kernel_launch(void* const* d_in, const int* in_sizes, int n_in,
                              void* d_out, int out_size)
{
    const float* x   = (const float*)d_in[0];
    const float* Wq  = (const float*)d_in[1];  const float* bq  = (const float*)d_in[2];
    const float* Wk  = (const float*)d_in[3];  const float* bk  = (const float*)d_in[4];
    const float* Wv  = (const float*)d_in[5];  const float* bv  = (const float*)d_in[6];
    const float* Wo  = (const float*)d_in[7];  const float* bo  = (const float*)d_in[8];
    const float* g1  = (const float*)d_in[9];  const float* b1  = (const float*)d_in[10];
    const float* W1f = (const float*)d_in[11]; const float* b1f = (const float*)d_in[12];
    const float* W2f = (const float*)d_in[13]; const float* b2f = (const float*)d_in[14];
    const float* g2  = (const float*)d_in[15]; const float* b2  = (const float*)d_in[16];
    const int*   sidx = (const int*)d_in[17];
    float* out = (float*)d_out;

    float *Qp, *Kp, *Vp, *ctxp, *attnp, *x1p, *ffhp, *Mp, *mvpp, *mvp, *mzp, *MZp, *cpp, *ctp;
    int* topp;
    __nv_bfloat16 *ah, *al, *wqh, *wql, *wkh, *wkl, *wvh, *wvl, *woh, *wol, *w1h, *w1l, *w2h, *w2l;
    cudaGetSymbolAddress((void**)&Qp,    g_Q);
    cudaGetSymbolAddress((void**)&Kp,    g_K);
    cudaGetSymbolAddress((void**)&Vp,    g_V);
    cudaGetSymbolAddress((void**)&ctxp,  g_ctx);
    cudaGetSymbolAddress((void**)&attnp, g_attn);
    cudaGetSymbolAddress((void**)&x1p,   g_x1);
    cudaGetSymbolAddress((void**)&ffhp,  g_ffh);
    cudaGetSymbolAddress((void**)&Mp,    g_Mm);
    cudaGetSymbolAddress((void**)&topp,  g_top);
    cudaGetSymbolAddress((void**)&mvpp,  g_mvpart);
    cudaGetSymbolAddress((void**)&mvp,   g_meanv);
    cudaGetSymbolAddress((void**)&mzp,   g_mzpart);
    cudaGetSymbolAddress((void**)&MZp,   g_MZ);
    cudaGetSymbolAddress((void**)&cpp,   g_cpart);
    cudaGetSymbolAddress((void**)&ctp,   g_ctxtop);
    cudaGetSymbolAddress((void**)&ah,  g_act_h);  cudaGetSymbolAddress((void**)&al,  g_act_l);
    cudaGetSymbolAddress((void**)&wqh, g_wq_h);   cudaGetSymbolAddress((void**)&wql, g_wq_l);
    cudaGetSymbolAddress((void**)&wkh, g_wk_h);   cudaGetSymbolAddress((void**)&wkl, g_wk_l);
    cudaGetSymbolAddress((void**)&wvh, g_wv_h);   cudaGetSymbolAddress((void**)&wvl, g_wv_l);
    cudaGetSymbolAddress((void**)&woh, g_wo_h);   cudaGetSymbolAddress((void**)&wol, g_wo_l);
    cudaGetSymbolAddress((void**)&w1h, g_w1_h);   cudaGetSymbolAddress((void**)&w1l, g_w1_l);
    cudaGetSymbolAddress((void**)&w2h, g_w2_h);   cudaGetSymbolAddress((void**)&w2l, g_w2_l);

    const int GEMM_SMEM = 2 * 4 * 16384;  // 131072
    cudaFuncSetAttribute(gemm_tc, cudaFuncAttributeMaxDynamicSharedMemorySize, GEMM_SMEM);

    // weight conversions (transposed splits)
    wsplit_t<<<(DD*DD + 255)/256, 256>>>(Wq,  wqh, wql, DD, DD);
    wsplit_t<<<(DD*DD + 255)/256, 256>>>(Wk,  wkh, wkl, DD, DD);
    wsplit_t<<<(DD*DD + 255)/256, 256>>>(Wv,  wvh, wvl, DD, DD);
    wsplit_t<<<(DD*DD + 255)/256, 256>>>(Wo,  woh, wol, DD, DD);
    wsplit_t<<<(DD*DFF + 255)/256, 256>>>(W1f, w1h, w1l, DD, DFF);
    wsplit_t<<<(DFF*DD + 255)/256, 256>>>(W2f, w2h, w2l, DFF, DD);

    // x split + QKV projections
    split_convert<<<(MROWS*DD + 255)/256, 256>>>(x, ah, al, MROWS*DD);
    gemm_tc<<<dim3(DD/128, MROWS/128), 256, GEMM_SMEM>>>(ah, al, wqh, wql, bq, Qp, MROWS, DD, DD, 0);
    gemm_tc<<<dim3(DD/128, MROWS/128), 256, GEMM_SMEM>>>(ah, al, wkh, wkl, bk, Kp, MROWS, DD, DD, 0);
    gemm_tc<<<dim3(DD/128, MROWS/128), 256, GEMM_SMEM>>>(ah, al, wvh, wvl, bv, Vp, MROWS, DD, DD, 0);

    // sparsity metric + top-k
    sampled_scores_kernel<<<dim3(LL, 64), 128>>>(Qp, Kp, sidx, Mp);
    topk_kernel<<<64, 512>>>(Mp, topp);

    // meanV
    meanv_part_kernel<<<dim3(32, BB), 512>>>(Vp, mvpp);
    meanv_reduce_kernel<<<BB, 512>>>(mvpp, mvp);

    // top-query attention
    attn_mz_kernel<<<dim3(4, 64), 128>>>(Qp, Kp, topp, mzp);
    attn_mz_combine<<<64, 128>>>(mzp, MZp);
    attn_ctx_kernel<<<dim3(8, 64, 4), 128>>>(Qp, Kp, Vp, topp, MZp, cpp);
    attn_ctx_combine<<<(64*UU*DH + 255)/256, 256>>>(cpp, MZp, ctp);

    // assemble ctx, O projection
    broadcast_meanv<<<(int)(((size_t)MROWS*DD + 255)/256), 256>>>(mvp, ctxp);
    scatter_ctxtop<<<dim3(UU, 64), 64>>>(ctp, topp, ctxp);
    split_convert<<<(MROWS*DD + 255)/256, 256>>>(ctxp, ah, al, MROWS*DD);
    gemm_tc<<<dim3(DD/128, MROWS/128), 256, GEMM_SMEM>>>(ah, al, woh, wol, bo, attnp, MROWS, DD, DD, 0);

    // LN1
    add_ln_kernel<<<MROWS, 128>>>(x, attnp, g1, b1, x1p);

    // FFN
    split_convert<<<(MROWS*DD + 255)/256, 256>>>(x1p, ah, al, MROWS*DD);
    gemm_tc<<<dim3(DFF/128, MROWS/128), 256, GEMM_SMEM>>>(ah, al, w1h, w1l, b1f, ffhp, MROWS, DFF, DD, 1);
    split_convert<<<(MROWS*DFF + 255)/256, 256>>>(ffhp, ah, al, MROWS*DFF);
    gemm_tc<<<dim3(DD/128, MROWS/128), 256, GEMM_SMEM>>>(ah, al, w2h, w2l, b2f, attnp, MROWS, DD, DFF, 0);

    // LN2 -> output
    add_ln_kernel<<<MROWS, 128>>>(x1p, attnp, g2, b2, out);
}

// round 12
// speedup vs baseline: 1.2500x; 1.0452x over previous
#include <cuda_runtime.h>
#include <cuda_bf16.h>
#include <math.h>
#include <stdint.h>

// Problem constants
#define BB 8
#define LL 4096
#define DD 512
#define HH 8
#define DH 64
#define DFF 2048
#define SK 128
#define UU 128
#define MROWS (BB*LL)   // 32768

// ---------------- scratch (device globals; no allocation allowed) -------------
__device__ __align__(16) float g_Q[MROWS*DD];
__device__ __align__(16) float g_K[MROWS*DD];
__device__ __align__(16) float g_V[MROWS*DD];
__device__ __align__(16) float g_ctx[MROWS*DD];
__device__ __align__(16) float g_attn[MROWS*DD];
__device__ __align__(16) float g_x1[MROWS*DD];
__device__ __align__(16) float g_Mm[64*LL];
__device__              int   g_top[64*UU];
__device__ __align__(16) float g_mvpart[BB*32*DD];
__device__ __align__(16) float g_meanv[BB*DD];
__device__ __align__(16) float g_mzpart[64*4*UU*2];
__device__ __align__(16) float g_MZ[64*UU*2];
__device__ __align__(16) float g_cpart[64*UU*4*DH];
__device__ __align__(16) float g_ctxtop[64*UU*DH];

// packed split-bf16 operands: act [M][3K] = [hi|lo|hi], weight [N][3K] = [hi|hi|lo]
__device__ __align__(16) __nv_bfloat16 g_apk[MROWS*3*DD];    // x / ctx / x1 (reused)
__device__ __align__(16) __nv_bfloat16 g_fpk[(size_t)MROWS*3*DFF];  // ffh packed
__device__ __align__(16) __nv_bfloat16 g_wqpk[DD*3*DD];
__device__ __align__(16) __nv_bfloat16 g_wkpk[DD*3*DD];
__device__ __align__(16) __nv_bfloat16 g_wvpk[DD*3*DD];
__device__ __align__(16) __nv_bfloat16 g_wopk[DD*3*DD];
__device__ __align__(16) __nv_bfloat16 g_w1pk[DFF*3*DD];
__device__ __align__(16) __nv_bfloat16 g_w2pk[DD*3*DFF];

// ===================== sm_80-baseline tensor helpers ==========================
__device__ __forceinline__ uint32_t smem_u32(const void* p) {
    uint32_t a;
    asm("{ .reg .u64 t; cvta.to.shared.u64 t, %1; cvt.u32.u64 %0, t; }" : "=r"(a) : "l"(p));
    return a;
}
__device__ __forceinline__ void cpa16(uint32_t s, const void* g) {
    asm volatile("cp.async.cg.shared.global [%0], [%1], 16;" :: "r"(s), "l"(g) : "memory");
}
__device__ __forceinline__ void ldm_x4(uint32_t* r, uint32_t a) {
    asm volatile("ldmatrix.sync.aligned.m8n8.x4.shared.b16 {%0,%1,%2,%3}, [%4];"
                 : "=r"(r[0]), "=r"(r[1]), "=r"(r[2]), "=r"(r[3]) : "r"(a));
}
__device__ __forceinline__ void mma_bf16(float* c, const uint32_t* a, uint32_t b0, uint32_t b1) {
    asm volatile("mma.sync.aligned.m16n8k16.row.col.f32.bf16.bf16.f32 "
                 "{%0,%1,%2,%3}, {%4,%5,%6,%7}, {%8,%9}, {%0,%1,%2,%3};"
                 : "+f"(c[0]), "+f"(c[1]), "+f"(c[2]), "+f"(c[3])
                 : "r"(a[0]), "r"(a[1]), "r"(a[2]), "r"(a[3]), "r"(b0), "r"(b1));
}

// ============ packed split-bf16 GEMM: C = A @ W + bias (+relu) ================
// A packed [M][Kp], W packed [N][Kp], Kp = 3K. Block 128x128, 8 warps (2x4),
// warp tile 64x32, BK=64, 3-stage cp.async pipeline. Smem 3*32KB = 96KB.
// Optional float C and/or packed-activation Cpk ([M][3N] = [hi|lo|hi]).
__global__ void __launch_bounds__(256, 2) gemm_tc(
    const __nv_bfloat16* __restrict__ A, const __nv_bfloat16* __restrict__ B,
    const float* __restrict__ bias, float* __restrict__ C,
    __nv_bfloat16* __restrict__ Cpk,
    int M, int N, int Kp, int relu)
{
    extern __shared__ char smem[];
    const int tid = threadIdx.x, lid = tid & 31, wid = tid >> 5;
    const int warp_m = wid & 1, warp_n = wid >> 1;   // 2 x 4 warps
    const int m0 = blockIdx.y * 128, n0 = blockIdx.x * 128;
    const uint32_t sb = smem_u32(smem);
    const int nch = Kp >> 6;

    auto issue = [&](int c, int s) {
        const int k0 = c << 6;
        const uint32_t base = sb + s * 32768;
        #pragma unroll
        for (int it = 0; it < 8; it++) {
            int i = it * 256 + tid;          // 0..2047: 2 tiles x 128 rows x 8 segs
            int tile = i >> 10, idx = i & 1023;
            int row = idx >> 3, seg = idx & 7;
            uint32_t off = row * 128 + seg * 16;
            uint32_t sw = off ^ ((off >> 3) & 0x70);
            const __nv_bfloat16* src = tile
                ? B + (size_t)(n0 + row) * Kp + k0 + seg * 8
                : A + (size_t)(m0 + row) * Kp + k0 + seg * 8;
            cpa16(base + tile * 16384 + sw, src);
        }
        asm volatile("cp.async.commit_group;" ::: "memory");
    };

    float acc[4][4][4];
    #pragma unroll
    for (int mi = 0; mi < 4; mi++)
        #pragma unroll
        for (int ni = 0; ni < 4; ni++)
            #pragma unroll
            for (int f = 0; f < 4; f++) acc[mi][ni][f] = 0.f;

    issue(0, 0);
    issue(1, 1);
    for (int c = 0; c < nch; c++) {
        if (c + 2 < nch) {
            issue(c + 2, (c + 2) % 3);
            asm volatile("cp.async.wait_group 2;" ::: "memory");
        } else if (c + 1 < nch) {
            asm volatile("cp.async.wait_group 1;" ::: "memory");
        } else {
            asm volatile("cp.async.wait_group 0;" ::: "memory");
        }
        __syncthreads();
        const uint32_t base = sb + (c % 3) * 32768;
        #pragma unroll
        for (int ks = 0; ks < 4; ks++) {
            uint32_t af[4][4], bfr[2][4];
            #pragma unroll
            for (int mi = 0; mi < 4; mi++) {
                int row = warp_m * 64 + mi * 16 + (lid & 15);
                uint32_t off = row * 128 + ks * 32 + (lid >> 4) * 16;
                ldm_x4(af[mi], base + (off ^ ((off >> 3) & 0x70)));
            }
            #pragma unroll
            for (int nj = 0; nj < 2; nj++) {
                int row = warp_n * 32 + nj * 16 + (lid & 15);
                uint32_t off = row * 128 + ks * 32 + (lid >> 4) * 16;
                ldm_x4(bfr[nj], base + 16384 + (off ^ ((off >> 3) & 0x70)));
            }
            // B x4 matrices: m0 rows0-7@k0, m1 rows8-15@k0, m2 rows0-7@k8, m3 rows8-15@k8
            #pragma unroll
            for (int mi = 0; mi < 4; mi++)
                #pragma unroll
                for (int ni = 0; ni < 4; ni++)
                    mma_bf16(acc[mi][ni], af[mi],
                             bfr[ni >> 1][ni & 1], bfr[ni >> 1][(ni & 1) + 2]);
        }
        __syncthreads();
    }

    // epilogue: C frag c0:(l/4, 2(l%4)) c1:+1col c2:+8row c3:+8row+1col
    const int grow = m0 + warp_m * 64;
    const int gcol = n0 + warp_n * 32;
    #pragma unroll
    for (int mi = 0; mi < 4; mi++)
        #pragma unroll
        for (int ni = 0; ni < 4; ni++) {
            int r = grow + mi * 16 + (lid >> 2);
            int cc = gcol + ni * 8 + (lid & 3) * 2;
            float b0 = bias[cc], b1 = bias[cc + 1];
            float v0 = acc[mi][ni][0] + b0;
            float v1 = acc[mi][ni][1] + b1;
            float v2 = acc[mi][ni][2] + b0;
            float v3 = acc[mi][ni][3] + b1;
            if (relu) {
                v0 = fmaxf(v0, 0.f); v1 = fmaxf(v1, 0.f);
                v2 = fmaxf(v2, 0.f); v3 = fmaxf(v3, 0.f);
            }
            if (C) {
                C[(size_t)r * N + cc]           = v0;
                C[(size_t)r * N + cc + 1]       = v1;
                C[(size_t)(r + 8) * N + cc]     = v2;
                C[(size_t)(r + 8) * N + cc + 1] = v3;
            }
            if (Cpk) {
                __nv_bfloat162 h, l;
                // row r
                h.x = __float2bfloat16(v0); h.y = __float2bfloat16(v1);
                l.x = __float2bfloat16(v0 - __bfloat162float(h.x));
                l.y = __float2bfloat16(v1 - __bfloat162float(h.y));
                size_t rb = (size_t)r * 3 * N + cc;
                *(__nv_bfloat162*)(Cpk + rb)         = h;
                *(__nv_bfloat162*)(Cpk + rb + N)     = l;
                *(__nv_bfloat162*)(Cpk + rb + 2 * N) = h;
                // row r+8
                h.x = __float2bfloat16(v2); h.y = __float2bfloat16(v3);
                l.x = __float2bfloat16(v2 - __bfloat162float(h.x));
                l.y = __float2bfloat16(v3 - __bfloat162float(h.y));
                size_t rb8 = (size_t)(r + 8) * 3 * N + cc;
                *(__nv_bfloat162*)(Cpk + rb8)         = h;
                *(__nv_bfloat162*)(Cpk + rb8 + N)     = l;
                *(__nv_bfloat162*)(Cpk + rb8 + 2 * N) = h;
            }
        }
}

// ---------------- packing kernels ---------------------------------------------
// activation pack: in [M][K] fp32 -> pk [M][3K] = [hi | lo | hi]
__global__ void act_pack(const float* __restrict__ in, __nv_bfloat16* __restrict__ pk,
                         int K, int n)
{
    int i = blockIdx.x * 256 + threadIdx.x;
    if (i >= n) return;
    int m = i / K, k = i - m * K;
    float v = in[i];
    __nv_bfloat16 h = __float2bfloat16(v);
    __nv_bfloat16 l = __float2bfloat16(v - __bfloat162float(h));
    size_t base = (size_t)m * 3 * K;
    pk[base + k] = h;
    pk[base + K + k] = l;
    pk[base + 2 * K + k] = h;
}
// weight pack: W [K][N] fp32 row-major -> pk [N][3K] = [hi | hi | lo]
__global__ void w_pack_t(const float* __restrict__ W, __nv_bfloat16* __restrict__ pk,
                         int K, int N)
{
    int i = blockIdx.x * 256 + threadIdx.x;
    if (i >= K * N) return;
    int n = i / K, k = i - n * K;
    float v = W[(size_t)k * N + n];
    __nv_bfloat16 h = __float2bfloat16(v);
    __nv_bfloat16 l = __float2bfloat16(v - __bfloat162float(h));
    size_t base = (size_t)n * 3 * K;
    pk[base + k] = h;
    pk[base + K + k] = h;
    pk[base + 2 * K + k] = l;
}

// ======================= attention-side kernels (unchanged) ===================
__global__ void sampled_scores_kernel(const float* __restrict__ Q, const float* __restrict__ Km,
                                      const int* __restrict__ sidx, float* __restrict__ Mout)
{
    int l = blockIdx.x, bh = blockIdx.y;
    int b = bh >> 3, h = bh & 7, t = threadIdx.x;  // 128 threads
    __shared__ float qs[64];
    __shared__ float red[128];
    __shared__ int is64;
    const float* qrow = Q + ((size_t)(b*LL + l))*DD + h*DH;
    if (t < 64) qs[t] = qrow[t];
    if (t == 0) is64 = 1;
    __syncthreads();
    if ((t & 1) && sidx[t] != 0) is64 = 0;
    __syncthreads();
    int li;
    if (is64) li = (int)(((const long long*)sidx)[t]) & (LL - 1);
    else      li = sidx[t] & (LL - 1);
    const float* krow = Km + ((size_t)(b*LL + li))*DD + h*DH;
    float dot = 0.f;
    #pragma unroll
    for (int d = 0; d < 64; d++) dot += qs[d]*krow[d];
    red[t] = dot; __syncthreads();
    for (int o = 64; o > 0; o >>= 1) { if (t < o) red[t] = fmaxf(red[t], red[t+o]); __syncthreads(); }
    float mx = red[0]; __syncthreads();
    red[t] = dot; __syncthreads();
    for (int o = 64; o > 0; o >>= 1) { if (t < o) red[t] += red[t+o]; __syncthreads(); }
    if (t == 0) Mout[(size_t)bh*LL + l] = mx - red[0]*(1.0f/128.0f);
}

__global__ void __launch_bounds__(512) topk_kernel(const float* __restrict__ Mv, int* __restrict__ top)
{
    __shared__ float val[4096];
    __shared__ int   idx[4096];
    int bh = blockIdx.x, t = threadIdx.x;
    for (int i = t; i < 4096; i += 512) { val[i] = Mv[(size_t)bh*LL + i]; idx[i] = i; }
    __syncthreads();
    for (int k = 2; k <= 4096; k <<= 1) {
        for (int j = k >> 1; j > 0; j >>= 1) {
            for (int i = t; i < 4096; i += 512) {
                int ixj = i ^ j;
                if (ixj > i) {
                    bool desc = ((i & k) == 0);
                    float vi = val[i], vj = val[ixj];
                    if ((vi < vj) == desc) {
                        val[i] = vj; val[ixj] = vi;
                        int tmp = idx[i]; idx[i] = idx[ixj]; idx[ixj] = tmp;
                    }
                }
            }
            __syncthreads();
        }
    }
    if (t < 128) top[bh*UU + t] = idx[t];
}

__global__ void meanv_part_kernel(const float* __restrict__ V, float* __restrict__ part)
{
    int chunk = blockIdx.x, b = blockIdx.y, t = threadIdx.x;
    float s = 0.f;
    int l0 = chunk * 128;
    for (int l = l0; l < l0 + 128; l++) s += V[((size_t)(b*LL + l))*DD + t];
    part[((size_t)b*32 + chunk)*DD + t] = s;
}
__global__ void meanv_reduce_kernel(const float* __restrict__ part, float* __restrict__ meanv)
{
    int b = blockIdx.x, t = threadIdx.x;
    float s = 0.f;
    for (int c = 0; c < 32; c++) s += part[((size_t)b*32 + c)*DD + t];
    meanv[b*DD + t] = s * (1.f/4096.f);
}

__global__ void __launch_bounds__(128) attn_mz_kernel(
    const float* __restrict__ Q, const float* __restrict__ Km,
    const int* __restrict__ top, float* __restrict__ mz)
{
    __shared__ float qs[128][65];
    __shared__ float kt[32][65];
    int chunk = blockIdx.x, bh = blockIdx.y;
    int b = bh >> 3, h = bh & 7, t = threadIdx.x;
    const float scale = 0.125f;
    for (int i = t; i < 128*64; i += 128) {
        int u = i >> 6, d = i & 63;
        int lq = top[bh*UU + u] & (LL - 1);
        qs[u][d] = Q[((size_t)(b*LL + lq))*DD + h*DH + d] * scale;
    }
    __syncthreads();
    float m = -1e30f, z = 0.f;
    int l0 = chunk * 1024;
    for (int lt = 0; lt < 1024; lt += 32) {
        for (int i = t; i < 32*64; i += 128) {
            int r = i >> 6, d = i & 63;
            kt[r][d] = Km[((size_t)(b*LL + l0 + lt + r))*DD + h*DH + d];
        }
        __syncthreads();
        for (int r = 0; r < 32; r++) {
            float s = 0.f;
            #pragma unroll
            for (int d = 0; d < 64; d++) s += qs[t][d]*kt[r][d];
            if (s > m) { z = z*__expf(m - s) + 1.f; m = s; }
            else       { z += __expf(s - m); }
        }
        __syncthreads();
    }
    mz[(((size_t)bh*4 + chunk)*UU + t)*2 + 0] = m;
    mz[(((size_t)bh*4 + chunk)*UU + t)*2 + 1] = z;
}

__global__ void attn_mz_combine(const float* __restrict__ mz, float* __restrict__ MZ)
{
    int bh = blockIdx.x, t = threadIdx.x;
    float m = -1e30f, z = 0.f;
    for (int c = 0; c < 4; c++) {
        float mc = mz[(((size_t)bh*4 + c)*UU + t)*2 + 0];
        float zc = mz[(((size_t)bh*4 + c)*UU + t)*2 + 1];
        float mm = fmaxf(m, mc);
        z = z*__expf(m - mm) + zc*__expf(mc - mm);
        m = mm;
    }
    MZ[((size_t)bh*UU + t)*2 + 0] = m;
    MZ[((size_t)bh*UU + t)*2 + 1] = z;
}

__global__ void __launch_bounds__(128) attn_ctx_kernel(
    const float* __restrict__ Q, const float* __restrict__ Km, const float* __restrict__ V,
    const int* __restrict__ top, const float* __restrict__ MZ, float* __restrict__ cpart)
{
    __shared__ float qs[16][65];
    __shared__ float kt[64][65];
    __shared__ float vt[64][66];
    __shared__ float ps[16][64];
    __shared__ float Ms[16];
    int ut = blockIdx.x, bh = blockIdx.y, chunk = blockIdx.z;
    int b = bh >> 3, h = bh & 7, t = threadIdx.x;
    const float scale = 0.125f;
    for (int i = t; i < 16*64; i += 128) {
        int u = i >> 6, d = i & 63;
        int lq = top[bh*UU + ut*16 + u] & (LL - 1);
        qs[u][d] = Q[((size_t)(b*LL + lq))*DD + h*DH + d] * scale;
    }
    if (t < 16) Ms[t] = MZ[((size_t)bh*UU + ut*16 + t)*2 + 0];
    __syncthreads();
    int qi = t >> 3, d0 = (t & 7) * 8;
    float acc[8] = {0,0,0,0,0,0,0,0};
    int l0 = chunk * 1024;
    for (int lt = 0; lt < 1024; lt += 64) {
        for (int i = t; i < 64*64; i += 128) {
            int r = i >> 6, d = i & 63;
            size_t base = ((size_t)(b*LL + l0 + lt + r))*DD + h*DH + d;
            kt[r][d] = Km[base];
            vt[r][d] = V[base];
        }
        __syncthreads();
        {
            int lbase = t & 7;
            #pragma unroll
            for (int i = 0; i < 8; i++) {
                int r = lbase*8 + i;
                float s = 0.f;
                #pragma unroll
                for (int d = 0; d < 64; d++) s += qs[qi][d]*kt[r][d];
                ps[qi][r] = __expf(s - Ms[qi]);
            }
        }
        __syncthreads();
        for (int r = 0; r < 64; r++) {
            float p = ps[qi][r];
            #pragma unroll
            for (int j = 0; j < 8; j++) acc[j] += p * vt[r][d0+j];
        }
        __syncthreads();
    }
    float* o = cpart + ((((size_t)bh*UU + ut*16 + qi)*4 + chunk)*DH) + d0;
    #pragma unroll
    for (int j = 0; j < 8; j++) o[j] = acc[j];
}

__global__ void attn_ctx_combine(const float* __restrict__ cpart, const float* __restrict__ MZ,
                                 float* __restrict__ ctxtop)
{
    int i = blockIdx.x*256 + threadIdx.x;
    if (i >= 64*UU*DH) return;
    int d = i & 63, u = (i >> 6) & 127, bh = i >> 13;
    float s = 0.f;
    for (int c = 0; c < 4; c++) s += cpart[(((size_t)bh*UU + u)*4 + c)*DH + d];
    float Z = MZ[((size_t)bh*UU + u)*2 + 1];
    ctxtop[i] = s / Z;
}

__global__ void broadcast_meanv(const float* __restrict__ meanv, float* __restrict__ ctx)
{
    size_t i = (size_t)blockIdx.x*256 + threadIdx.x;
    if (i >= (size_t)MROWS*DD) return;
    int col = (int)(i & 511);
    int row = (int)(i >> 9);
    int b = row >> 12;
    ctx[i] = meanv[b*DD + col];
}
__global__ void scatter_ctxtop(const float* __restrict__ ctxtop, const int* __restrict__ top,
                               float* __restrict__ ctx)
{
    int u = blockIdx.x, bh = blockIdx.y, t = threadIdx.x;
    int b = bh >> 3, h = bh & 7;
    int l = top[bh*UU + u] & (LL - 1);
    ctx[((size_t)(b*LL + l))*DD + h*DH + t] = ctxtop[((size_t)bh*UU + u)*DH + t];
}

// -------- fused residual-add + LayerNorm (optional packed output) -------------
__global__ void __launch_bounds__(128) add_ln_kernel(
    const float* __restrict__ a, const float* __restrict__ r,
    const float* __restrict__ g, const float* __restrict__ be,
    float* __restrict__ out, __nv_bfloat16* __restrict__ pk)
{
    int row = blockIdx.x, t = threadIdx.x;
    __shared__ float red[128];
    size_t base = (size_t)row * DD;
    float4 av = *(const float4*)(a + base + t*4);
    float4 rv = *(const float4*)(r + base + t*4);
    float x0 = av.x + rv.x, x1 = av.y + rv.y, x2 = av.z + rv.z, x3 = av.w + rv.w;
    red[t] = x0 + x1 + x2 + x3; __syncthreads();
    for (int o = 64; o > 0; o >>= 1) { if (t < o) red[t] += red[t+o]; __syncthreads(); }
    float mean = red[0] * (1.f/512.f); __syncthreads();
    float d0 = x0 - mean, d1 = x1 - mean, d2 = x2 - mean, d3 = x3 - mean;
    red[t] = d0*d0 + d1*d1 + d2*d2 + d3*d3; __syncthreads();
    for (int o = 64; o > 0; o >>= 1) { if (t < o) red[t] += red[t+o]; __syncthreads(); }
    float inv = rsqrtf(red[0]*(1.f/512.f) + 1e-6f);
    float4 gv = *(const float4*)(g + t*4);
    float4 bv = *(const float4*)(be + t*4);
    float4 y;
    y.x = d0*inv*gv.x + bv.x;
    y.y = d1*inv*gv.y + bv.y;
    y.z = d2*inv*gv.z + bv.z;
    y.w = d3*inv*gv.w + bv.w;
    *(float4*)(out + base + t*4) = y;
    if (pk) {
        __nv_bfloat162 h01, h23, l01, l23;
        h01.x = __float2bfloat16(y.x); h01.y = __float2bfloat16(y.y);
        h23.x = __float2bfloat16(y.z); h23.y = __float2bfloat16(y.w);
        l01.x = __float2bfloat16(y.x - __bfloat162float(h01.x));
        l01.y = __float2bfloat16(y.y - __bfloat162float(h01.y));
        l23.x = __float2bfloat16(y.z - __bfloat162float(h23.x));
        l23.y = __float2bfloat16(y.w - __bfloat162float(h23.y));
        size_t rb = (size_t)row * (3*DD) + t*4;
        *(__nv_bfloat162*)(pk + rb)            = h01;
        *(__nv_bfloat162*)(pk + rb + 2)        = h23;
        *(__nv_bfloat162*)(pk + rb + DD)       = l01;
        *(__nv_bfloat162*)(pk + rb + DD + 2)   = l23;
        *(__nv_bfloat162*)(pk + rb + 2*DD)     = h01;
        *(__nv_bfloat162*)(pk + rb + 2*DD + 2) = h23;
    }
}

// ------------------------------- launch ---------------------------------------
extern "C" void kernel_launch(void* const* d_in, const int* in_sizes, int n_in,
                              void* d_out, int out_size)
{
    const float* x   = (const float*)d_in[0];
    const float* Wq  = (const float*)d_in[1];  const float* bq  = (const float*)d_in[2];
    const float* Wk  = (const float*)d_in[3];  const float* bk  = (const float*)d_in[4];
    const float* Wv  = (const float*)d_in[5];  const float* bv  = (const float*)d_in[6];
    const float* Wo  = (const float*)d_in[7];  const float* bo  = (const float*)d_in[8];
    const float* g1  = (const float*)d_in[9];  const float* b1  = (const float*)d_in[10];
    const float* W1f = (const float*)d_in[11]; const float* b1f = (const float*)d_in[12];
    const float* W2f = (const float*)d_in[13]; const float* b2f = (const float*)d_in[14];
    const float* g2  = (const float*)d_in[15]; const float* b2  = (const float*)d_in[16];
    const int*   sidx = (const int*)d_in[17];
    float* out = (float*)d_out;

    float *Qp, *Kp, *Vp, *ctxp, *attnp, *x1p, *Mp, *mvpp, *mvp, *mzp, *MZp, *cpp, *ctp;
    int* topp;
    __nv_bfloat16 *apk, *fpk, *wqpk, *wkpk, *wvpk, *wopk, *w1pk, *w2pk;
    cudaGetSymbolAddress((void**)&Qp,    g_Q);
    cudaGetSymbolAddress((void**)&Kp,    g_K);
    cudaGetSymbolAddress((void**)&Vp,    g_V);
    cudaGetSymbolAddress((void**)&ctxp,  g_ctx);
    cudaGetSymbolAddress((void**)&attnp, g_attn);
    cudaGetSymbolAddress((void**)&x1p,   g_x1);
    cudaGetSymbolAddress((void**)&Mp,    g_Mm);
    cudaGetSymbolAddress((void**)&topp,  g_top);
    cudaGetSymbolAddress((void**)&mvpp,  g_mvpart);
    cudaGetSymbolAddress((void**)&mvp,   g_meanv);
    cudaGetSymbolAddress((void**)&mzp,   g_mzpart);
    cudaGetSymbolAddress((void**)&MZp,   g_MZ);
    cudaGetSymbolAddress((void**)&cpp,   g_cpart);
    cudaGetSymbolAddress((void**)&ctp,   g_ctxtop);
    cudaGetSymbolAddress((void**)&apk,  g_apk);
    cudaGetSymbolAddress((void**)&fpk,  g_fpk);
    cudaGetSymbolAddress((void**)&wqpk, g_wqpk);
    cudaGetSymbolAddress((void**)&wkpk, g_wkpk);
    cudaGetSymbolAddress((void**)&wvpk, g_wvpk);
    cudaGetSymbolAddress((void**)&wopk, g_wopk);
    cudaGetSymbolAddress((void**)&w1pk, g_w1pk);
    cudaGetSymbolAddress((void**)&w2pk, g_w2pk);

    const int GEMM_SMEM = 3 * 32768;  // 98304
    cudaFuncSetAttribute(gemm_tc, cudaFuncAttributeMaxDynamicSharedMemorySize, GEMM_SMEM);

    const int KP_D  = 3 * DD;    // 1536
    const int KP_FF = 3 * DFF;   // 6144

    // weight packs
    w_pack_t<<<(DD*DD + 255)/256, 256>>>(Wq,  wqpk, DD, DD);
    w_pack_t<<<(DD*DD + 255)/256, 256>>>(Wk,  wkpk, DD, DD);
    w_pack_t<<<(DD*DD + 255)/256, 256>>>(Wv,  wvpk, DD, DD);
    w_pack_t<<<(DD*DD + 255)/256, 256>>>(Wo,  wopk, DD, DD);
    w_pack_t<<<(DD*DFF + 255)/256, 256>>>(W1f, w1pk, DD, DFF);
    w_pack_t<<<(DFF*DD + 255)/256, 256>>>(W2f, w2pk, DFF, DD);

    // x pack + QKV projections
    act_pack<<<(MROWS*DD + 255)/256, 256>>>(x, apk, DD, MROWS*DD);
    gemm_tc<<<dim3(DD/128, MROWS/128), 256, GEMM_SMEM>>>(apk, wqpk, bq, Qp, (__nv_bfloat16*)0, MROWS, DD, KP_D, 0);
    gemm_tc<<<dim3(DD/128, MROWS/128), 256, GEMM_SMEM>>>(apk, wkpk, bk, Kp, (__nv_bfloat16*)0, MROWS, DD, KP_D, 0);
    gemm_tc<<<dim3(DD/128, MROWS/128), 256, GEMM_SMEM>>>(apk, wvpk, bv, Vp, (__nv_bfloat16*)0, MROWS, DD, KP_D, 0);

    // sparsity metric + top-k
    sampled_scores_kernel<<<dim3(LL, 64), 128>>>(Qp, Kp, sidx, Mp);
    topk_kernel<<<64, 512>>>(Mp, topp);

    // meanV
    meanv_part_kernel<<<dim3(32, BB), 512>>>(Vp, mvpp);
    meanv_reduce_kernel<<<BB, 512>>>(mvpp, mvp);

    // top-query attention
    attn_mz_kernel<<<dim3(4, 64), 128>>>(Qp, Kp, topp, mzp);
    attn_mz_combine<<<64, 128>>>(mzp, MZp);
    attn_ctx_kernel<<<dim3(8, 64, 4), 128>>>(Qp, Kp, Vp, topp, MZp, cpp);
    attn_ctx_combine<<<(64*UU*DH + 255)/256, 256>>>(cpp, MZp, ctp);

    // assemble ctx, O projection
    broadcast_meanv<<<(int)(((size_t)MROWS*DD + 255)/256), 256>>>(mvp, ctxp);
    scatter_ctxtop<<<dim3(UU, 64), 64>>>(ctp, topp, ctxp);
    act_pack<<<(MROWS*DD + 255)/256, 256>>>(ctxp, apk, DD, MROWS*DD);
    gemm_tc<<<dim3(DD/128, MROWS/128), 256, GEMM_SMEM>>>(apk, wopk, bo, attnp, (__nv_bfloat16*)0, MROWS, DD, KP_D, 0);

    // LN1 (float + packed)
    add_ln_kernel<<<MROWS, 128>>>(x, attnp, g1, b1, x1p, apk);

    // FFN1: packed output only (relu applied pre-pack)
    gemm_tc<<<dim3(DFF/128, MROWS/128), 256, GEMM_SMEM>>>(apk, w1pk, b1f, (float*)0, fpk, MROWS, DFF, KP_D, 1);
    // FFN2: float output
    gemm_tc<<<dim3(DD/128, MROWS/128), 256, GEMM_SMEM>>>(fpk, w2pk, b2f, attnp, (__nv_bfloat16*)0, MROWS, DD, KP_FF, 0);

    // LN2 -> output
    add_ln_kernel<<<MROWS, 128>>>(x1p, attnp, g2, b2, out, (__nv_bfloat16*)0);
}